// round 16
// baseline (speedup 1.0000x reference)
#include <cuda_runtime.h>
#include <stdint.h>

// QLinearLayerSign hybrid v3: persistent IMMA CTAs (1/SM, tensor pipe) +
// churning popc CTAs (ALU pipe). Disjoint N split:
//   IMMA:  n in [0, 1280)   via 160 persistent CTAs x 8 tiles (128x64)
//   POPC:  n in [1280, 4096) via 5632 CTAs (64x64)
// Exact: A in {0,1}, B/W in {-1,+1}, |acc| <= 4096.

#define BATCH 8192
#define INF   4096
#define OUTF  4096
#define KW    (INF / 32)

#define N_IMMA 1280

// IMMA: CTA tile 128x64, warp tile 32x32, BK=64, 2-stage, persistent.
#define I_BM 128
#define I_BN 64
#define I_BK 64
#define I_KCH (INF / I_BK)          // 64
#define RS 80
#define I_STG ((I_BM + I_BN) * RS)  // 15360
#define I_TILES_N (N_IMMA / I_BN)   // 20
#define I_TILES (64 * I_TILES_N)    // 1280
#define I_PERSIST 160
#define I_PER_CTA (I_TILES / I_PERSIST)  // 8

// POPC: CTA 64x64, 4x4/thread, BKW=32 words, 2-stage.
#define P_BM 64
#define P_BN 64
#define P_BKW 32
#define P_KCH (KW / P_BKW)          // 4
#define P_STGX (P_BM * 128)         // 8192
#define P_STG  (P_STGX + P_BN * 128)  // 16384
#define P_CTAS ((BATCH / P_BM) * ((OUTF - N_IMMA) / P_BN))  // 128*44 = 5632

#define SM_TOTAL (2 * P_STG)        // 32768 (>= 2*I_STG = 30720)
#define GRID_TOTAL (I_PERSIST + P_CTAS)  // 5792

__device__ int8_t   g_X8[(size_t)BATCH * INF];
__device__ int8_t   g_W8[(size_t)OUTF * INF];
__device__ uint32_t g_Xb[(size_t)BATCH * KW];
__device__ uint32_t g_Wb[(size_t)OUTF * KW];
__device__ int      g_Xr[BATCH];

__device__ __forceinline__ uint32_t smem_u32(const void* p) {
    uint32_t a;
    asm("{ .reg .u64 t; cvta.to.shared.u64 t, %1; cvt.u32.u64 %0, t; }" : "=r"(a) : "l"(p));
    return a;
}
__device__ __forceinline__ void cp16(uint32_t dst, const void* src) {
    asm volatile("cp.async.cg.shared.global [%0], [%1], 16;" :: "r"(dst), "l"(src));
}
__device__ __forceinline__ void cp_commit() {
    asm volatile("cp.async.commit_group;" ::: "memory");
}
template <int N> __device__ __forceinline__ void cp_wait() {
    asm volatile("cp.async.wait_group %0;" :: "n"(N) : "memory");
}
__device__ __forceinline__ void ldm_x4(uint32_t* r, uint32_t addr) {
    asm volatile("ldmatrix.sync.aligned.m8n8.x4.shared.b16 {%0,%1,%2,%3}, [%4];"
                 : "=r"(r[0]), "=r"(r[1]), "=r"(r[2]), "=r"(r[3]) : "r"(addr));
}
__device__ __forceinline__ void imma_op(int* d, const uint32_t* a, const uint32_t* b) {
    asm volatile(
        "mma.sync.aligned.m16n8k32.row.col.s32.s8.s8.s32 "
        "{%0,%1,%2,%3}, {%4,%5,%6,%7}, {%8,%9}, {%0,%1,%2,%3};"
        : "+r"(d[0]), "+r"(d[1]), "+r"(d[2]), "+r"(d[3])
        : "r"(a[0]), "r"(a[1]), "r"(a[2]), "r"(a[3]), "r"(b[0]), "r"(b[1]));
}

// ---------------------------------------------------------------------------
// Fused prologue: fp32 -> s8 bytes AND bitmask words in one pass.
// ---------------------------------------------------------------------------
template <int MODE>
__global__ __launch_bounds__(256) void fused_pack_kernel(
    const float* __restrict__ src, int8_t* __restrict__ d8,
    uint32_t* __restrict__ dbits)
{
    const int gw   = (int)(blockIdx.x * 8 + (threadIdx.x >> 5));
    const int lane = threadIdx.x & 31;
    float4 f = *reinterpret_cast<const float4*>(src + (size_t)gw * 128 + lane * 4);
    uint32_t s8;
    if (MODE == 0)
        s8 = (f.x > 0.f ? 1u : 0u) | ((f.y > 0.f ? 1u : 0u) << 8) |
             ((f.z > 0.f ? 1u : 0u) << 16) | ((f.w > 0.f ? 1u : 0u) << 24);
    else
        s8 = (f.x > 0.f ? 1u : 0xFFu) | ((f.y > 0.f ? 1u : 0xFFu) << 8) |
             ((f.z > 0.f ? 1u : 0xFFu) << 16) | ((f.w > 0.f ? 1u : 0xFFu) << 24);
    reinterpret_cast<uint32_t*>(d8)[(size_t)gw * 32 + lane] = s8;
    uint32_t nib = (f.x > 0.f ? 1u : 0u) | (f.y > 0.f ? 2u : 0u) |
                   (f.z > 0.f ? 4u : 0u) | (f.w > 0.f ? 8u : 0u);
    uint32_t v = nib << ((lane & 7) * 4);
    v |= __shfl_xor_sync(0xFFFFFFFFu, v, 1);
    v |= __shfl_xor_sync(0xFFFFFFFFu, v, 2);
    v |= __shfl_xor_sync(0xFFFFFFFFu, v, 4);
    uint32_t w0 = __shfl_sync(0xFFFFFFFFu, v, 0);
    uint32_t w1 = __shfl_sync(0xFFFFFFFFu, v, 8);
    uint32_t w2 = __shfl_sync(0xFFFFFFFFu, v, 16);
    uint32_t w3 = __shfl_sync(0xFFFFFFFFu, v, 24);
    if (lane == 0)
        *reinterpret_cast<uint4*>(dbits + (size_t)gw * 4) = make_uint4(w0, w1, w2, w3);
}

__global__ __launch_bounds__(256) void row_popc_kernel(
    const uint32_t* __restrict__ Xb, int* __restrict__ Xr, int rows)
{
    int row  = (int)(blockIdx.x * 8 + (threadIdx.x >> 5));
    int lane = threadIdx.x & 31;
    if (row >= rows) return;
    const uint32_t* p = Xb + (size_t)row * KW;
    int s = 0;
    #pragma unroll
    for (int i = 0; i < KW / 32; i++) s += __popc(p[lane + i * 32]);
    #pragma unroll
    for (int o = 16; o; o >>= 1) s += __shfl_xor_sync(0xFFFFFFFFu, s, o);
    if (lane == 0) Xr[row] = s;
}

// ---------------------------------------------------------------------------
// Hybrid kernel v3: bid < I_PERSIST -> persistent IMMA; else popc.
// ---------------------------------------------------------------------------
__global__ __launch_bounds__(256, 4)
void hybrid_kernel(const int8_t*   __restrict__ A8,
                   const int8_t*   __restrict__ B8,
                   const uint32_t* __restrict__ Xb,
                   const uint32_t* __restrict__ Wb,
                   const int*      __restrict__ Xr,
                   float*          __restrict__ out)
{
    extern __shared__ char smem[];
    const uint32_t sb = smem_u32(smem);
    const int tid = threadIdx.x;
    const int bid = blockIdx.x;

    if (bid < I_PERSIST) {
        // ========== persistent IMMA: 8 tiles of 128x64, n in [0,1280) ==========
        const int lane = tid & 31;
        const int w    = tid >> 5;
        const int wm   = w & 3;
        const int wn   = w >> 2;
        const int lrow = lane & 15;
        const int lhi  = (lane >> 4) * 16;
        const int rg   = lane >> 2, tg = lane & 3;

        for (int t = 0; t < I_PER_CTA; ++t) {
            const int tile = bid + t * I_PERSIST;        // 0..1279
            const int m0 = (tile / I_TILES_N) * I_BM;
            const int n0 = (tile % I_TILES_N) * I_BN;

            int acc[2][4][4];
            #pragma unroll
            for (int mt = 0; mt < 2; ++mt)
                #pragma unroll
                for (int nt = 0; nt < 4; ++nt)
                    #pragma unroll
                    for (int k = 0; k < 4; ++k) acc[mt][nt][k] = 0;

            auto load_chunk = [&](int c, int s) {
                const uint32_t sa  = sb + s * I_STG;
                const uint32_t sbB = sa + I_BM * RS;
                #pragma unroll
                for (int it = 0; it < 2; ++it) {
                    int id = it * 256 + tid;
                    int row = id >> 2, seg = id & 3;
                    cp16(sa + row * RS + seg * 16,
                         A8 + (size_t)(m0 + row) * INF + c * I_BK + seg * 16);
                }
                {
                    int row = tid >> 2, seg = tid & 3;
                    cp16(sbB + row * RS + seg * 16,
                         B8 + (size_t)(n0 + row) * INF + c * I_BK + seg * 16);
                }
                cp_commit();
            };

            load_chunk(0, 0);

            for (int c = 0; c < I_KCH; ++c) {
                const int s = c & 1;
                if (c + 1 < I_KCH) { load_chunk(c + 1, s ^ 1); cp_wait<1>(); }
                else               { cp_wait<0>(); }
                __syncthreads();

                const uint32_t sa  = sb + s * I_STG;
                const uint32_t sbB = sa + I_BM * RS;

                #pragma unroll
                for (int ks = 0; ks < 2; ++ks) {
                    const int ko = ks * 32;
                    uint32_t a[2][4];
                    #pragma unroll
                    for (int mt = 0; mt < 2; ++mt)
                        ldm_x4(a[mt], sa + (wm * 32 + mt * 16 + lrow) * RS + lhi + ko);
                    uint32_t blo[4], bhi[4];
                    ldm_x4(blo, sbB + (wn * 32 + lane) * RS + ko);
                    ldm_x4(bhi, sbB + (wn * 32 + lane) * RS + 16 + ko);
                    #pragma unroll
                    for (int mt = 0; mt < 2; ++mt)
                        #pragma unroll
                        for (int nt = 0; nt < 4; ++nt) {
                            uint32_t b2[2] = { blo[nt], bhi[nt] };
                            imma_op(acc[mt][nt], a[mt], b2);
                        }
                }
                __syncthreads();
            }

            #pragma unroll
            for (int mt = 0; mt < 2; ++mt) {
                const int r0 = m0 + wm * 32 + mt * 16 + rg;
                #pragma unroll
                for (int nt = 0; nt < 4; ++nt) {
                    const int cc = n0 + wn * 32 + nt * 8 + tg * 2;
                    float2 v0 = make_float2((float)acc[mt][nt][0], (float)acc[mt][nt][1]);
                    float2 v1 = make_float2((float)acc[mt][nt][2], (float)acc[mt][nt][3]);
                    *reinterpret_cast<float2*>(&out[(size_t)r0 * OUTF + cc])       = v0;
                    *reinterpret_cast<float2*>(&out[(size_t)(r0 + 8) * OUTF + cc]) = v1;
                }
            }
            __syncthreads();   // protect smem reuse across tiles
        }
    } else {
        // ================= POPC path: n in [N_IMMA, 4096) =================
        const int j  = bid - I_PERSIST;                // 0..5631
        const int m0 = (j / 44) * P_BM;
        const int n0 = N_IMMA + (j % 44) * P_BN;
        const int tx = tid & 15;
        const int ty = tid >> 4;
        const int sA = (ty >> 1) & 7;
        const int sB = (tx >> 1) & 7;

        auto load_chunk = [&](int c, int s) {
            const uint32_t bx = sb + s * P_STG;
            const uint32_t bw = bx + P_STGX;
            #pragma unroll
            for (int it = 0; it < 2; ++it) {
                int id  = it * 256 + tid;
                int row = id >> 3, seg = id & 7;
                int sw  = (seg ^ ((row >> 3) & 7)) * 16;
                cp16(bx + row * 128 + sw, Xb + (size_t)(m0 + row) * KW + c * P_BKW + seg * 4);
            }
            #pragma unroll
            for (int it = 0; it < 2; ++it) {
                int id  = it * 256 + tid;
                int row = id >> 3, seg = id & 7;
                int sw  = (seg ^ ((row >> 3) & 7)) * 16;
                cp16(bw + row * 128 + sw, Wb + (size_t)(n0 + row) * KW + c * P_BKW + seg * 4);
            }
            cp_commit();
        };

        int acc[4][4];
        #pragma unroll
        for (int a = 0; a < 4; ++a)
            #pragma unroll
            for (int b = 0; b < 4; ++b) acc[a][b] = 0;

        load_chunk(0, 0);

        for (int c = 0; c < P_KCH; ++c) {
            const int s = c & 1;
            if (c + 1 < P_KCH) { load_chunk(c + 1, s ^ 1); cp_wait<1>(); }
            else               { cp_wait<0>(); }
            __syncthreads();

            const char* xs = smem + s * P_STG + (ty * 4) * 128;
            const char* ws = smem + s * P_STG + P_STGX + (tx * 4) * 128;

            #pragma unroll
            for (int k4 = 0; k4 < 8; ++k4) {
                const int ca = (k4 ^ sA) * 16;
                const int cb = (k4 ^ sB) * 16;
                uint4 a0 = *reinterpret_cast<const uint4*>(xs + 0 * 128 + ca);
                uint4 a1 = *reinterpret_cast<const uint4*>(xs + 1 * 128 + ca);
                uint4 a2 = *reinterpret_cast<const uint4*>(xs + 2 * 128 + ca);
                uint4 a3 = *reinterpret_cast<const uint4*>(xs + 3 * 128 + ca);
                #pragma unroll
                for (int nt = 0; nt < 4; ++nt) {
                    uint4 b = *reinterpret_cast<const uint4*>(ws + nt * 128 + cb);
                    acc[0][nt] += __popc(a0.x & b.x) + __popc(a0.y & b.y)
                                + __popc(a0.z & b.z) + __popc(a0.w & b.w);
                    acc[1][nt] += __popc(a1.x & b.x) + __popc(a1.y & b.y)
                                + __popc(a1.z & b.z) + __popc(a1.w & b.w);
                    acc[2][nt] += __popc(a2.x & b.x) + __popc(a2.y & b.y)
                                + __popc(a2.z & b.z) + __popc(a2.w & b.w);
                    acc[3][nt] += __popc(a3.x & b.x) + __popc(a3.y & b.y)
                                + __popc(a3.z & b.z) + __popc(a3.w & b.w);
                }
            }
            __syncthreads();
        }

        #pragma unroll
        for (int mt = 0; mt < 4; ++mt) {
            const int m = m0 + ty * 4 + mt;
            const int R = Xr[m];
            float4 v;
            v.x = (float)(2 * acc[mt][0] - R);
            v.y = (float)(2 * acc[mt][1] - R);
            v.z = (float)(2 * acc[mt][2] - R);
            v.w = (float)(2 * acc[mt][3] - R);
            *reinterpret_cast<float4*>(&out[(size_t)m * OUTF + n0 + tx * 4]) = v;
        }
    }
}

// ---------------------------------------------------------------------------
extern "C" void kernel_launch(void* const* d_in, const int* in_sizes, int n_in,
                              void* d_out, int out_size)
{
    const float* x = (const float*)d_in[0];
    const float* W = (const float*)d_in[1];
    if (n_in >= 2 && in_sizes[0] == OUTF * INF && in_sizes[1] == BATCH * INF) {
        x = (const float*)d_in[1];
        W = (const float*)d_in[0];
    }
    float* out = (float*)d_out;

    int8_t* X8; int8_t* W8; uint32_t* Xb; uint32_t* Wb; int* Xr;
    cudaGetSymbolAddress((void**)&X8, g_X8);
    cudaGetSymbolAddress((void**)&W8, g_W8);
    cudaGetSymbolAddress((void**)&Xb, g_Xb);
    cudaGetSymbolAddress((void**)&Wb, g_Wb);
    cudaGetSymbolAddress((void**)&Xr, g_Xr);

    fused_pack_kernel<0><<<(int)((size_t)BATCH * INF / 128 / 8), 256>>>(x, X8, Xb);
    fused_pack_kernel<1><<<(int)((size_t)OUTF * INF / 128 / 8), 256>>>(W, W8, Wb);
    row_popc_kernel<<<BATCH / 8, 256>>>(Xb, Xr, BATCH);

    cudaFuncSetAttribute(hybrid_kernel,
                         cudaFuncAttributeMaxDynamicSharedMemorySize, SM_TOTAL);
    hybrid_kernel<<<GRID_TOTAL, 256, SM_TOTAL>>>(X8, W8, Xb, Wb, Xr, out);
}

// round 17
// speedup vs baseline: 1.2789x; 1.2789x over previous
#include <cuda_runtime.h>
#include <stdint.h>

// QLinearLayerSign hybrid v4: R15 interleaved hybrid + conflict-free popc
// warp layout (1-phase LDS for both A and B fragments).
//   IMMA:  n in [0, 1280)     POPC: n in [1280, 4096)
// Exact: A in {0,1}, B/W in {-1,+1}, |acc| <= 4096.

#define BATCH 8192
#define INF   4096
#define OUTF  4096
#define KW    (INF / 32)

#define N_IMMA 1280

// IMMA: CTA 128x64, warp tile 32x32, BK=64, 2-stage.
#define I_BM 128
#define I_BN 64
#define I_BK 64
#define I_KCH (INF / I_BK)          // 64
#define RS 80
#define I_STG ((I_BM + I_BN) * RS)  // 15360
// POPC: CTA 64x64, 4x4/thread, BKW=32 words, 2-stage.
#define P_BM 64
#define P_BN 64
#define P_BKW 32
#define P_KCH (KW / P_BKW)          // 4
#define P_STGX (P_BM * 128)         // 8192
#define P_STG  (P_STGX + P_BN * 128)  // 16384

#define SM_TOTAL (2 * P_STG)        // 32768 (>= 2*I_STG = 30720)
#define GRID_TOTAL 6912             // 27*256; slot<5 -> imma(1280), else popc(5632)

__device__ int8_t   g_X8[(size_t)BATCH * INF];
__device__ int8_t   g_W8[(size_t)OUTF * INF];
__device__ uint32_t g_Xb[(size_t)BATCH * KW];
__device__ uint32_t g_Wb[(size_t)OUTF * KW];
__device__ int      g_Xr[BATCH];

__device__ __forceinline__ uint32_t smem_u32(const void* p) {
    uint32_t a;
    asm("{ .reg .u64 t; cvta.to.shared.u64 t, %1; cvt.u32.u64 %0, t; }" : "=r"(a) : "l"(p));
    return a;
}
__device__ __forceinline__ void cp16(uint32_t dst, const void* src) {
    asm volatile("cp.async.cg.shared.global [%0], [%1], 16;" :: "r"(dst), "l"(src));
}
__device__ __forceinline__ void cp_commit() {
    asm volatile("cp.async.commit_group;" ::: "memory");
}
template <int N> __device__ __forceinline__ void cp_wait() {
    asm volatile("cp.async.wait_group %0;" :: "n"(N) : "memory");
}
__device__ __forceinline__ void ldm_x4(uint32_t* r, uint32_t addr) {
    asm volatile("ldmatrix.sync.aligned.m8n8.x4.shared.b16 {%0,%1,%2,%3}, [%4];"
                 : "=r"(r[0]), "=r"(r[1]), "=r"(r[2]), "=r"(r[3]) : "r"(addr));
}
__device__ __forceinline__ void imma_op(int* d, const uint32_t* a, const uint32_t* b) {
    asm volatile(
        "mma.sync.aligned.m16n8k32.row.col.s32.s8.s8.s32 "
        "{%0,%1,%2,%3}, {%4,%5,%6,%7}, {%8,%9}, {%0,%1,%2,%3};"
        : "+r"(d[0]), "+r"(d[1]), "+r"(d[2]), "+r"(d[3])
        : "r"(a[0]), "r"(a[1]), "r"(a[2]), "r"(a[3]), "r"(b[0]), "r"(b[1]));
}

// ---------------------------------------------------------------------------
// Fused prologue: fp32 -> s8 bytes AND bitmask words in one pass.
// ---------------------------------------------------------------------------
template <int MODE>
__global__ __launch_bounds__(256) void fused_pack_kernel(
    const float* __restrict__ src, int8_t* __restrict__ d8,
    uint32_t* __restrict__ dbits)
{
    const int gw   = (int)(blockIdx.x * 8 + (threadIdx.x >> 5));
    const int lane = threadIdx.x & 31;
    float4 f = *reinterpret_cast<const float4*>(src + (size_t)gw * 128 + lane * 4);
    uint32_t s8;
    if (MODE == 0)
        s8 = (f.x > 0.f ? 1u : 0u) | ((f.y > 0.f ? 1u : 0u) << 8) |
             ((f.z > 0.f ? 1u : 0u) << 16) | ((f.w > 0.f ? 1u : 0u) << 24);
    else
        s8 = (f.x > 0.f ? 1u : 0xFFu) | ((f.y > 0.f ? 1u : 0xFFu) << 8) |
             ((f.z > 0.f ? 1u : 0xFFu) << 16) | ((f.w > 0.f ? 1u : 0xFFu) << 24);
    reinterpret_cast<uint32_t*>(d8)[(size_t)gw * 32 + lane] = s8;
    uint32_t nib = (f.x > 0.f ? 1u : 0u) | (f.y > 0.f ? 2u : 0u) |
                   (f.z > 0.f ? 4u : 0u) | (f.w > 0.f ? 8u : 0u);
    uint32_t v = nib << ((lane & 7) * 4);
    v |= __shfl_xor_sync(0xFFFFFFFFu, v, 1);
    v |= __shfl_xor_sync(0xFFFFFFFFu, v, 2);
    v |= __shfl_xor_sync(0xFFFFFFFFu, v, 4);
    uint32_t w0 = __shfl_sync(0xFFFFFFFFu, v, 0);
    uint32_t w1 = __shfl_sync(0xFFFFFFFFu, v, 8);
    uint32_t w2 = __shfl_sync(0xFFFFFFFFu, v, 16);
    uint32_t w3 = __shfl_sync(0xFFFFFFFFu, v, 24);
    if (lane == 0)
        *reinterpret_cast<uint4*>(dbits + (size_t)gw * 4) = make_uint4(w0, w1, w2, w3);
}

__global__ __launch_bounds__(256) void row_popc_kernel(
    const uint32_t* __restrict__ Xb, int* __restrict__ Xr, int rows)
{
    int row  = (int)(blockIdx.x * 8 + (threadIdx.x >> 5));
    int lane = threadIdx.x & 31;
    if (row >= rows) return;
    const uint32_t* p = Xb + (size_t)row * KW;
    int s = 0;
    #pragma unroll
    for (int i = 0; i < KW / 32; i++) s += __popc(p[lane + i * 32]);
    #pragma unroll
    for (int o = 16; o; o >>= 1) s += __shfl_xor_sync(0xFFFFFFFFu, s, o);
    if (lane == 0) Xr[row] = s;
}

// ---------------------------------------------------------------------------
// Hybrid kernel v4 (4 CTAs/SM, slot-interleaved, conflict-free popc LDS).
// ---------------------------------------------------------------------------
__global__ __launch_bounds__(256, 4)
void hybrid_kernel(const int8_t*   __restrict__ A8,
                   const int8_t*   __restrict__ B8,
                   const uint32_t* __restrict__ Xb,
                   const uint32_t* __restrict__ Wb,
                   const int*      __restrict__ Xr,
                   float*          __restrict__ out)
{
    extern __shared__ char smem[];
    const uint32_t sb = smem_u32(smem);
    const int tid  = threadIdx.x;
    const int bid  = blockIdx.x;
    const int slot = bid % 27;

    if (slot < 5) {
        // ================= IMMA path: n in [0, N_IMMA), 2-stage =================
        const int i     = (bid / 27) * 5 + slot;       // 0..1279
        const int m0    = (i / 20) * I_BM;
        const int n0    = (i % 20) * I_BN;
        const int lane  = tid & 31;
        const int w     = tid >> 5;
        const int wm    = w & 3;
        const int wn    = w >> 2;
        const int lrow  = lane & 15;
        const int lhi   = (lane >> 4) * 16;

        int acc[2][4][4];
        #pragma unroll
        for (int mt = 0; mt < 2; ++mt)
            #pragma unroll
            for (int nt = 0; nt < 4; ++nt)
                #pragma unroll
                for (int k = 0; k < 4; ++k) acc[mt][nt][k] = 0;

        auto load_chunk = [&](int c, int s) {
            const uint32_t sa  = sb + s * I_STG;
            const uint32_t sbB = sa + I_BM * RS;
            #pragma unroll
            for (int it = 0; it < 2; ++it) {
                int id = it * 256 + tid;
                int row = id >> 2, seg = id & 3;
                cp16(sa + row * RS + seg * 16,
                     A8 + (size_t)(m0 + row) * INF + c * I_BK + seg * 16);
            }
            {
                int row = tid >> 2, seg = tid & 3;
                cp16(sbB + row * RS + seg * 16,
                     B8 + (size_t)(n0 + row) * INF + c * I_BK + seg * 16);
            }
            cp_commit();
        };

        load_chunk(0, 0);

        for (int c = 0; c < I_KCH; ++c) {
            const int s = c & 1;
            if (c + 1 < I_KCH) { load_chunk(c + 1, s ^ 1); cp_wait<1>(); }
            else               { cp_wait<0>(); }
            __syncthreads();

            const uint32_t sa  = sb + s * I_STG;
            const uint32_t sbB = sa + I_BM * RS;

            #pragma unroll
            for (int ks = 0; ks < 2; ++ks) {
                const int ko = ks * 32;
                uint32_t a[2][4];
                #pragma unroll
                for (int mt = 0; mt < 2; ++mt)
                    ldm_x4(a[mt], sa + (wm * 32 + mt * 16 + lrow) * RS + lhi + ko);
                uint32_t blo[4], bhi[4];
                ldm_x4(blo, sbB + (wn * 32 + lane) * RS + ko);
                ldm_x4(bhi, sbB + (wn * 32 + lane) * RS + 16 + ko);
                #pragma unroll
                for (int mt = 0; mt < 2; ++mt)
                    #pragma unroll
                    for (int nt = 0; nt < 4; ++nt) {
                        uint32_t b2[2] = { blo[nt], bhi[nt] };
                        imma_op(acc[mt][nt], a[mt], b2);
                    }
            }
            __syncthreads();
        }

        const int rg = lane >> 2, tg = lane & 3;
        #pragma unroll
        for (int mt = 0; mt < 2; ++mt) {
            const int r0 = m0 + wm * 32 + mt * 16 + rg;
            #pragma unroll
            for (int nt = 0; nt < 4; ++nt) {
                const int cc = n0 + wn * 32 + nt * 8 + tg * 2;
                float2 v0 = make_float2((float)acc[mt][nt][0], (float)acc[mt][nt][1]);
                float2 v1 = make_float2((float)acc[mt][nt][2], (float)acc[mt][nt][3]);
                *reinterpret_cast<float2*>(&out[(size_t)r0 * OUTF + cc])       = v0;
                *reinterpret_cast<float2*>(&out[(size_t)(r0 + 8) * OUTF + cc]) = v1;
            }
        }
    } else {
        // ================= POPC path: n in [N_IMMA, 4096) =================
        const int j  = (bid / 27) * 22 + (slot - 5);   // 0..5631
        const int m0 = (j / 44) * P_BM;
        const int n0 = N_IMMA + (j % 44) * P_BN;
        const int lane = tid & 31;
        const int warp = tid >> 5;
        // Conflict-free warp layout: per warp, b-frag swizzle keys (tx>>1)
        // = lane&7 all distinct (1 phase); a-frag keys (ty>>1) 4 distinct (1 phase).
        const int tx = ((lane & 7) << 1) | (warp & 1);   // 0..15
        const int ty = ((lane >> 3) << 2) | (warp >> 1); // 0..15
        const int sA = (ty >> 1) & 7;
        const int sB = (tx >> 1) & 7;

        auto load_chunk = [&](int c, int s) {
            const uint32_t bx = sb + s * P_STG;
            const uint32_t bw = bx + P_STGX;
            #pragma unroll
            for (int it = 0; it < 2; ++it) {
                int id  = it * 256 + tid;
                int row = id >> 3, seg = id & 7;
                int sw  = (seg ^ ((row >> 3) & 7)) * 16;
                cp16(bx + row * 128 + sw, Xb + (size_t)(m0 + row) * KW + c * P_BKW + seg * 4);
            }
            #pragma unroll
            for (int it = 0; it < 2; ++it) {
                int id  = it * 256 + tid;
                int row = id >> 3, seg = id & 7;
                int sw  = (seg ^ ((row >> 3) & 7)) * 16;
                cp16(bw + row * 128 + sw, Wb + (size_t)(n0 + row) * KW + c * P_BKW + seg * 4);
            }
            cp_commit();
        };

        int acc[4][4];
        #pragma unroll
        for (int a = 0; a < 4; ++a)
            #pragma unroll
            for (int b = 0; b < 4; ++b) acc[a][b] = 0;

        load_chunk(0, 0);

        for (int c = 0; c < P_KCH; ++c) {
            const int s = c & 1;
            if (c + 1 < P_KCH) { load_chunk(c + 1, s ^ 1); cp_wait<1>(); }
            else               { cp_wait<0>(); }
            __syncthreads();

            const char* xs = smem + s * P_STG + (ty * 4) * 128;
            const char* ws = smem + s * P_STG + P_STGX + (tx * 4) * 128;

            #pragma unroll
            for (int k4 = 0; k4 < 8; ++k4) {
                const int ca = (k4 ^ sA) * 16;
                const int cb = (k4 ^ sB) * 16;
                uint4 a0 = *reinterpret_cast<const uint4*>(xs + 0 * 128 + ca);
                uint4 a1 = *reinterpret_cast<const uint4*>(xs + 1 * 128 + ca);
                uint4 a2 = *reinterpret_cast<const uint4*>(xs + 2 * 128 + ca);
                uint4 a3 = *reinterpret_cast<const uint4*>(xs + 3 * 128 + ca);
                #pragma unroll
                for (int nt = 0; nt < 4; ++nt) {
                    uint4 b = *reinterpret_cast<const uint4*>(ws + nt * 128 + cb);
                    acc[0][nt] += __popc(a0.x & b.x) + __popc(a0.y & b.y)
                                + __popc(a0.z & b.z) + __popc(a0.w & b.w);
                    acc[1][nt] += __popc(a1.x & b.x) + __popc(a1.y & b.y)
                                + __popc(a1.z & b.z) + __popc(a1.w & b.w);
                    acc[2][nt] += __popc(a2.x & b.x) + __popc(a2.y & b.y)
                                + __popc(a2.z & b.z) + __popc(a2.w & b.w);
                    acc[3][nt] += __popc(a3.x & b.x) + __popc(a3.y & b.y)
                                + __popc(a3.z & b.z) + __popc(a3.w & b.w);
                }
            }
            __syncthreads();
        }

        #pragma unroll
        for (int mt = 0; mt < 4; ++mt) {
            const int m = m0 + ty * 4 + mt;
            const int R = Xr[m];
            float4 v;
            v.x = (float)(2 * acc[mt][0] - R);
            v.y = (float)(2 * acc[mt][1] - R);
            v.z = (float)(2 * acc[mt][2] - R);
            v.w = (float)(2 * acc[mt][3] - R);
            *reinterpret_cast<float4*>(&out[(size_t)m * OUTF + n0 + tx * 4]) = v;
        }
    }
}

// ---------------------------------------------------------------------------
extern "C" void kernel_launch(void* const* d_in, const int* in_sizes, int n_in,
                              void* d_out, int out_size)
{
    const float* x = (const float*)d_in[0];
    const float* W = (const float*)d_in[1];
    if (n_in >= 2 && in_sizes[0] == OUTF * INF && in_sizes[1] == BATCH * INF) {
        x = (const float*)d_in[1];
        W = (const float*)d_in[0];
    }
    float* out = (float*)d_out;

    int8_t* X8; int8_t* W8; uint32_t* Xb; uint32_t* Wb; int* Xr;
    cudaGetSymbolAddress((void**)&X8, g_X8);
    cudaGetSymbolAddress((void**)&W8, g_W8);
    cudaGetSymbolAddress((void**)&Xb, g_Xb);
    cudaGetSymbolAddress((void**)&Wb, g_Wb);
    cudaGetSymbolAddress((void**)&Xr, g_Xr);

    fused_pack_kernel<0><<<(int)((size_t)BATCH * INF / 128 / 8), 256>>>(x, X8, Xb);
    fused_pack_kernel<1><<<(int)((size_t)OUTF * INF / 128 / 8), 256>>>(W, W8, Wb);
    row_popc_kernel<<<BATCH / 8, 256>>>(Xb, Xr, BATCH);

    cudaFuncSetAttribute(hybrid_kernel,
                         cudaFuncAttributeMaxDynamicSharedMemorySize, SM_TOTAL);
    hybrid_kernel<<<GRID_TOTAL, 256, SM_TOTAL>>>(X8, W8, Xb, Wb, Xr, out);
}